// round 10
// baseline (speedup 1.0000x reference)
#include <cuda_runtime.h>
#include <math.h>
#include <stdint.h>

// Problem constants
#define BATCH 4
#define T     4096
#define C     1024
#define H     64
#define TOTROWS (BATCH * T)          // 16384
#define SCALE 0.03125f               // C^-0.5 = 1/32

// Scratch for projected q, k, v
__device__ float g_q[TOTROWS * H];
__device__ float g_k[TOTROWS * H];
__device__ float g_v[TOTROWS * H];

// ---------------------------------------------------------------------------
// tf32 helpers (warp-level mma.sync — compiles for compute_103, HMMA pipe)
// ---------------------------------------------------------------------------
__device__ __forceinline__ uint32_t f32_to_tf32(float x) {
    uint32_t y;
    asm("cvt.rna.tf32.f32 %0, %1;" : "=r"(y) : "f"(x));
    return y;
}

// D = A(16x8,row) * B(8x8,col) + D ; tf32 inputs, fp32 accum
__device__ __forceinline__ void mma_tf32(float c[4],
                                         uint32_t a0, uint32_t a1, uint32_t a2, uint32_t a3,
                                         uint32_t b0, uint32_t b1) {
    asm volatile(
        "mma.sync.aligned.m16n8k8.row.col.f32.tf32.tf32.f32 "
        "{%0,%1,%2,%3}, {%4,%5,%6,%7}, {%8,%9}, {%0,%1,%2,%3};"
        : "+f"(c[0]), "+f"(c[1]), "+f"(c[2]), "+f"(c[3])
        : "r"(a0), "r"(a1), "r"(a2), "r"(a3), "r"(b0), "r"(b1));
}

// ===========================================================================
// Kernel A: fused QKV projection with mma.sync tf32 (validated in round 7).
// ===========================================================================
#define XS_STR 68     // uint32 stride
#define WS_STR 200    // uint32 stride
#define PJ_SMEM_WORDS (128 * XS_STR + 64 * WS_STR)

__global__ __launch_bounds__(256, 1) void proj_mma_kernel(
    const float* __restrict__ x,
    const float* __restrict__ Wq,
    const float* __restrict__ Wk,
    const float* __restrict__ Wv)
{
    extern __shared__ uint32_t smw[];
    uint32_t* Xs = smw;                   // [128][XS_STR]
    uint32_t* Ws = smw + 128 * XS_STR;    // [64][WS_STR], cols 0..191 used

    const int tid  = threadIdx.x;
    const int wid  = tid >> 5;
    const int lane = tid & 31;
    const int r    = lane >> 2;           // 0..7
    const int cq   = lane & 3;            // 0..3
    const int w16  = wid * 16;
    const int m0   = blockIdx.x * 128;

    float acc[24][4];
    #pragma unroll
    for (int n = 0; n < 24; n++)
        #pragma unroll
        for (int j = 0; j < 4; j++) acc[n][j] = 0.f;

    for (int ch = 0; ch < 16; ch++) {
        const int k0 = ch * 64;
        __syncthreads();

        // x tile: 128 rows x 64 cols -> Xs (tf32)
        #pragma unroll
        for (int i = 0; i < 8; i++) {
            int f   = i * 256 + tid;            // 0..2047 float4
            int row = f >> 4;
            int c4  = (f & 15) * 4;
            float4 v = *(const float4*)(x + (size_t)(m0 + row) * C + k0 + c4);
            *(uint4*)&Xs[row * XS_STR + c4] = make_uint4(
                f32_to_tf32(v.x), f32_to_tf32(v.y), f32_to_tf32(v.z), f32_to_tf32(v.w));
        }
        // W tiles: 64 k x (3*64) n -> Ws (tf32)
        #pragma unroll
        for (int i = 0; i < 12; i++) {
            int f  = i * 256 + tid;             // 0..3071 float4
            int w  = f >> 10;                   // 0..2
            int rr = f & 1023;
            int kk = rr >> 4;                   // 0..63
            int n4 = (rr & 15) * 4;             // 0..60
            const float* Wp = (w == 0) ? Wq : (w == 1) ? Wk : Wv;
            float4 v = *(const float4*)(Wp + (size_t)(k0 + kk) * H + n4);
            *(uint4*)&Ws[kk * WS_STR + w * 64 + n4] = make_uint4(
                f32_to_tf32(v.x), f32_to_tf32(v.y), f32_to_tf32(v.z), f32_to_tf32(v.w));
        }
        __syncthreads();

        #pragma unroll
        for (int ks = 0; ks < 8; ks++) {
            uint32_t a0 = Xs[(w16 + r)     * XS_STR + ks * 8 + cq];
            uint32_t a1 = Xs[(w16 + r + 8) * XS_STR + ks * 8 + cq];
            uint32_t a2 = Xs[(w16 + r)     * XS_STR + ks * 8 + cq + 4];
            uint32_t a3 = Xs[(w16 + r + 8) * XS_STR + ks * 8 + cq + 4];
            #pragma unroll
            for (int n = 0; n < 24; n++) {
                uint32_t b0 = Ws[(ks * 8 + cq)     * WS_STR + n * 8 + r];
                uint32_t b1 = Ws[(ks * 8 + cq + 4) * WS_STR + n * 8 + r];
                mma_tf32(acc[n], a0, a1, a2, a3, b0, b1);
            }
        }
    }

    // epilogue
    const int tr0 = m0 + w16 + r;
    #pragma unroll
    for (int n = 0; n < 24; n++) {
        int which = n >> 3;
        int col   = (n * 8) & 63;
        float* op = (which == 0) ? g_q : (which == 1) ? g_k : g_v;
        *(float2*)(op + (size_t)tr0       * H + col + 2 * cq) = make_float2(acc[n][0], acc[n][1]);
        *(float2*)(op + (size_t)(tr0 + 8) * H + col + 2 * cq) = make_float2(acc[n][2], acc[n][3]);
    }
}

// ===========================================================================
// Kernel B: causal flash attention with mma.sync tf32 (FA2 style).
// 1024 blocks... no: 256 blocks x 128 threads, ONE 64-row q-tile per block,
// longest-first ordering (qt = 63 - bx/4), 2 CTAs/SM for latency hiding.
// ===========================================================================
#define QS_STR 68
#define KT_STR 72
#define VS_STR 72
#define PS_STR 68
#define AT_SMEM_WORDS (64*QS_STR + 64*KT_STR + 64*VS_STR + 4*16*PS_STR)

__global__ __launch_bounds__(128, 2) void attn_mma_kernel(float* __restrict__ out)
{
    extern __shared__ uint32_t sm[];
    uint32_t* Qs = sm;                          // [64][QS_STR] tf32 (scaled)
    uint32_t* Kt = Qs + 64 * QS_STR;            // [64 dim][KT_STR keys] tf32
    uint32_t* Vs = Kt + 64 * KT_STR;            // [64 s][VS_STR h] tf32
    uint32_t* Ps = Vs + 64 * VS_STR;            // per-warp [16][PS_STR] tf32

    // longest-first: bx 0..3 -> qt 63 (64 tiles), bx 252..255 -> qt 0 (1 tile)
    const int qt   = 63 - (blockIdx.x >> 2);
    const int b    = blockIdx.x & 3;
    const int tid  = threadIdx.x;
    const int wid  = tid >> 5;
    const int lane = tid & 31;
    const int r    = lane >> 2;                 // 0..7
    const int cq   = lane & 3;                  // 0..3
    const int w16  = wid * 16;
    uint32_t* Pw   = Ps + wid * 16 * PS_STR;

    const float* __restrict__ qg = g_q + (size_t)b * T * H;
    const float* __restrict__ kg = g_k + (size_t)b * T * H;
    const float* __restrict__ vg = g_v + (size_t)b * T * H;

    const int q0 = qt * 64;
    const int ntiles = qt + 1;

    // load Q tile: 64 rows x 64 cols = 1024 float4 (scaled, tf32)
    #pragma unroll
    for (int i = 0; i < 8; i++) {
        int f   = i * 128 + tid;            // 0..1023 float4
        int row = f >> 4;                   // 0..63
        int c4  = (f & 15) * 4;
        float4 v = *(const float4*)(qg + (size_t)(q0 + row) * H + c4);
        *(uint4*)&Qs[row * QS_STR + c4] = make_uint4(
            f32_to_tf32(v.x * SCALE), f32_to_tf32(v.y * SCALE),
            f32_to_tf32(v.z * SCALE), f32_to_tf32(v.w * SCALE));
    }
    __syncthreads();

    // Q A-fragments: persistent in registers
    uint32_t qa[8][4];
    #pragma unroll
    for (int ks = 0; ks < 8; ks++) {
        qa[ks][0] = Qs[(w16 + r)     * QS_STR + ks * 8 + cq];
        qa[ks][1] = Qs[(w16 + r + 8) * QS_STR + ks * 8 + cq];
        qa[ks][2] = Qs[(w16 + r)     * QS_STR + ks * 8 + cq + 4];
        qa[ks][3] = Qs[(w16 + r + 8) * QS_STR + ks * 8 + cq + 4];
    }

    float O[8][4];
    #pragma unroll
    for (int n = 0; n < 8; n++)
        #pragma unroll
        for (int j = 0; j < 4; j++) O[n][j] = 0.f;
    float m0h = -1e30f, m1h = -1e30f, l0 = 0.f, l1 = 0.f;

    const int tr0g = q0 + w16 + r;
    const int tr1g = tr0g + 8;

    for (int tile = 0; tile < ntiles; tile++) {
        const int s0 = tile * 64;

        __syncthreads();   // everyone done reading Kt/Vs of previous tile
        #pragma unroll
        for (int i = 0; i < 8; i++) {
            int f   = i * 128 + tid;        // 1024 float4
            int row = f >> 4;               // key index 0..63
            int c4  = (f & 15) * 4;         // dim base
            float4 kv = *(const float4*)(kg + (size_t)(s0 + row) * H + c4);
            Kt[(c4 + 0) * KT_STR + row] = f32_to_tf32(kv.x);
            Kt[(c4 + 1) * KT_STR + row] = f32_to_tf32(kv.y);
            Kt[(c4 + 2) * KT_STR + row] = f32_to_tf32(kv.z);
            Kt[(c4 + 3) * KT_STR + row] = f32_to_tf32(kv.w);
            float4 vv = *(const float4*)(vg + (size_t)(s0 + row) * H + c4);
            *(uint4*)&Vs[row * VS_STR + c4] = make_uint4(
                f32_to_tf32(vv.x), f32_to_tf32(vv.y),
                f32_to_tf32(vv.z), f32_to_tf32(vv.w));
        }
        __syncthreads();

        // ---- S = Q * K^T ----
        float S[8][4];
        #pragma unroll
        for (int n = 0; n < 8; n++) {
            #pragma unroll
            for (int j = 0; j < 4; j++) S[n][j] = 0.f;
        }
        #pragma unroll
        for (int ks = 0; ks < 8; ks++) {
            #pragma unroll
            for (int n = 0; n < 8; n++) {
                uint32_t b0 = Kt[(ks * 8 + cq)     * KT_STR + n * 8 + r];
                uint32_t b1 = Kt[(ks * 8 + cq + 4) * KT_STR + n * 8 + r];
                mma_tf32(S[n], qa[ks][0], qa[ks][1], qa[ks][2], qa[ks][3], b0, b1);
            }
        }

        // ---- causal mask on diagonal tile ----
        if (tile == qt) {
            #pragma unroll
            for (int n = 0; n < 8; n++) {
                int col0 = s0 + n * 8 + 2 * cq;
                int col1 = col0 + 1;
                if (col0 > tr0g) S[n][0] = -1e30f;
                if (col1 > tr0g) S[n][1] = -1e30f;
                if (col0 > tr1g) S[n][2] = -1e30f;
                if (col1 > tr1g) S[n][3] = -1e30f;
            }
        }

        // ---- online softmax (rows split: [0,1] row r; [2,3] row r+8) ----
        float mx0 = -1e30f, mx1 = -1e30f;
        #pragma unroll
        for (int n = 0; n < 8; n++) {
            mx0 = fmaxf(mx0, fmaxf(S[n][0], S[n][1]));
            mx1 = fmaxf(mx1, fmaxf(S[n][2], S[n][3]));
        }
        mx0 = fmaxf(mx0, __shfl_xor_sync(0xffffffffu, mx0, 1));
        mx0 = fmaxf(mx0, __shfl_xor_sync(0xffffffffu, mx0, 2));
        mx1 = fmaxf(mx1, __shfl_xor_sync(0xffffffffu, mx1, 1));
        mx1 = fmaxf(mx1, __shfl_xor_sync(0xffffffffu, mx1, 2));

        float mn0 = fmaxf(m0h, mx0);
        float mn1 = fmaxf(m1h, mx1);
        float corr0 = __expf(m0h - mn0);
        float corr1 = __expf(m1h - mn1);
        m0h = mn0; m1h = mn1;

        float rs0 = 0.f, rs1 = 0.f;
        #pragma unroll
        for (int n = 0; n < 8; n++) {
            uint32_t p00 = f32_to_tf32(__expf(S[n][0] - mn0));
            uint32_t p01 = f32_to_tf32(__expf(S[n][1] - mn0));
            uint32_t p10 = f32_to_tf32(__expf(S[n][2] - mn1));
            uint32_t p11 = f32_to_tf32(__expf(S[n][3] - mn1));
            rs0 += __uint_as_float(p00) + __uint_as_float(p01);
            rs1 += __uint_as_float(p10) + __uint_as_float(p11);
            *(uint2*)&Pw[r       * PS_STR + n * 8 + 2 * cq] = make_uint2(p00, p01);
            *(uint2*)&Pw[(r + 8) * PS_STR + n * 8 + 2 * cq] = make_uint2(p10, p11);
        }
        rs0 += __shfl_xor_sync(0xffffffffu, rs0, 1);
        rs0 += __shfl_xor_sync(0xffffffffu, rs0, 2);
        rs1 += __shfl_xor_sync(0xffffffffu, rs1, 1);
        rs1 += __shfl_xor_sync(0xffffffffu, rs1, 2);
        l0 = l0 * corr0 + rs0;
        l1 = l1 * corr1 + rs1;

        #pragma unroll
        for (int n = 0; n < 8; n++) {
            O[n][0] *= corr0; O[n][1] *= corr0;
            O[n][2] *= corr1; O[n][3] *= corr1;
        }
        __syncwarp();

        // ---- O += P * V ----
        #pragma unroll
        for (int ks = 0; ks < 8; ks++) {
            uint32_t a0 = Pw[r       * PS_STR + ks * 8 + cq];
            uint32_t a1 = Pw[(r + 8) * PS_STR + ks * 8 + cq];
            uint32_t a2 = Pw[r       * PS_STR + ks * 8 + cq + 4];
            uint32_t a3 = Pw[(r + 8) * PS_STR + ks * 8 + cq + 4];
            #pragma unroll
            for (int n = 0; n < 8; n++) {
                uint32_t b0 = Vs[(ks * 8 + cq)     * VS_STR + n * 8 + r];
                uint32_t b1 = Vs[(ks * 8 + cq + 4) * VS_STR + n * 8 + r];
                mma_tf32(O[n], a0, a1, a2, a3, b0, b1);
            }
        }
        __syncwarp();
    }

    // ---- epilogue ----
    float inv0 = 1.0f / l0;
    float inv1 = 1.0f / l1;
    float* o0 = out + ((size_t)b * T + tr0g) * H;
    float* o1 = out + ((size_t)b * T + tr1g) * H;
    #pragma unroll
    for (int n = 0; n < 8; n++) {
        *(float2*)(o0 + n * 8 + 2 * cq) = make_float2(O[n][0] * inv0, O[n][1] * inv0);
        *(float2*)(o1 + n * 8 + 2 * cq) = make_float2(O[n][2] * inv1, O[n][3] * inv1);
    }
}

// ---------------------------------------------------------------------------
extern "C" void kernel_launch(void* const* d_in, const int* in_sizes, int n_in,
                              void* d_out, int out_size)
{
    const float* x  = (const float*)d_in[0];
    const float* Wq = (const float*)d_in[1];
    const float* Wk = (const float*)d_in[2];
    const float* Wv = (const float*)d_in[3];
    float* out = (float*)d_out;

    static int attr_set = 0;
    const int pj_smem = PJ_SMEM_WORDS * 4;
    const int at_smem = AT_SMEM_WORDS * 4;
    if (!attr_set) {
        cudaFuncSetAttribute(proj_mma_kernel,
                             cudaFuncAttributeMaxDynamicSharedMemorySize, pj_smem);
        cudaFuncSetAttribute(attn_mma_kernel,
                             cudaFuncAttributeMaxDynamicSharedMemorySize, at_smem);
        attr_set = 1;
    }

    proj_mma_kernel<<<TOTROWS / 128, 256, pj_smem>>>(x, Wq, Wk, Wv);
    attn_mma_kernel<<<256, 128, at_smem>>>(out);
}

// round 11
// speedup vs baseline: 1.5876x; 1.5876x over previous
#include <cuda_runtime.h>
#include <math.h>
#include <stdint.h>

// Problem constants
#define BATCH 4
#define T     4096
#define C     1024
#define H     64
#define TOTROWS (BATCH * T)          // 16384
#define SCALE 0.03125f               // C^-0.5 = 1/32

// Scratch for projected q, k, v
__device__ float g_q[TOTROWS * H];
__device__ float g_k[TOTROWS * H];
__device__ float g_v[TOTROWS * H];

// ---------------------------------------------------------------------------
// tf32 helpers (warp-level mma.sync — compiles for compute_103, HMMA pipe)
// ---------------------------------------------------------------------------
__device__ __forceinline__ uint32_t f32_to_tf32(float x) {
    uint32_t y;
    asm("cvt.rna.tf32.f32 %0, %1;" : "=r"(y) : "f"(x));
    return y;
}

// D = A(16x8,row) * B(8x8,col) + D ; tf32 inputs, fp32 accum
__device__ __forceinline__ void mma_tf32(float c[4],
                                         uint32_t a0, uint32_t a1, uint32_t a2, uint32_t a3,
                                         uint32_t b0, uint32_t b1) {
    asm volatile(
        "mma.sync.aligned.m16n8k8.row.col.f32.tf32.tf32.f32 "
        "{%0,%1,%2,%3}, {%4,%5,%6,%7}, {%8,%9}, {%0,%1,%2,%3};"
        : "+f"(c[0]), "+f"(c[1]), "+f"(c[2]), "+f"(c[3])
        : "r"(a0), "r"(a1), "r"(a2), "r"(a3), "r"(b0), "r"(b1));
}

// ===========================================================================
// Kernel A: fused QKV projection with mma.sync tf32 (validated in round 7).
// ===========================================================================
#define XS_STR 68     // uint32 stride
#define WS_STR 200    // uint32 stride
#define PJ_SMEM_WORDS (128 * XS_STR + 64 * WS_STR)

__global__ __launch_bounds__(256, 1) void proj_mma_kernel(
    const float* __restrict__ x,
    const float* __restrict__ Wq,
    const float* __restrict__ Wk,
    const float* __restrict__ Wv)
{
    extern __shared__ uint32_t smw[];
    uint32_t* Xs = smw;                   // [128][XS_STR]
    uint32_t* Ws = smw + 128 * XS_STR;    // [64][WS_STR], cols 0..191 used

    const int tid  = threadIdx.x;
    const int wid  = tid >> 5;
    const int lane = tid & 31;
    const int r    = lane >> 2;           // 0..7
    const int cq   = lane & 3;            // 0..3
    const int w16  = wid * 16;
    const int m0   = blockIdx.x * 128;

    float acc[24][4];
    #pragma unroll
    for (int n = 0; n < 24; n++)
        #pragma unroll
        for (int j = 0; j < 4; j++) acc[n][j] = 0.f;

    for (int ch = 0; ch < 16; ch++) {
        const int k0 = ch * 64;
        __syncthreads();

        // x tile: 128 rows x 64 cols -> Xs (tf32)
        #pragma unroll
        for (int i = 0; i < 8; i++) {
            int f   = i * 256 + tid;            // 0..2047 float4
            int row = f >> 4;
            int c4  = (f & 15) * 4;
            float4 v = *(const float4*)(x + (size_t)(m0 + row) * C + k0 + c4);
            *(uint4*)&Xs[row * XS_STR + c4] = make_uint4(
                f32_to_tf32(v.x), f32_to_tf32(v.y), f32_to_tf32(v.z), f32_to_tf32(v.w));
        }
        // W tiles: 64 k x (3*64) n -> Ws (tf32)
        #pragma unroll
        for (int i = 0; i < 12; i++) {
            int f  = i * 256 + tid;             // 0..3071 float4
            int w  = f >> 10;                   // 0..2
            int rr = f & 1023;
            int kk = rr >> 4;                   // 0..63
            int n4 = (rr & 15) * 4;             // 0..60
            const float* Wp = (w == 0) ? Wq : (w == 1) ? Wk : Wv;
            float4 v = *(const float4*)(Wp + (size_t)(k0 + kk) * H + n4);
            *(uint4*)&Ws[kk * WS_STR + w * 64 + n4] = make_uint4(
                f32_to_tf32(v.x), f32_to_tf32(v.y), f32_to_tf32(v.z), f32_to_tf32(v.w));
        }
        __syncthreads();

        #pragma unroll
        for (int ks = 0; ks < 8; ks++) {
            uint32_t a0 = Xs[(w16 + r)     * XS_STR + ks * 8 + cq];
            uint32_t a1 = Xs[(w16 + r + 8) * XS_STR + ks * 8 + cq];
            uint32_t a2 = Xs[(w16 + r)     * XS_STR + ks * 8 + cq + 4];
            uint32_t a3 = Xs[(w16 + r + 8) * XS_STR + ks * 8 + cq + 4];
            #pragma unroll
            for (int n = 0; n < 24; n++) {
                uint32_t b0 = Ws[(ks * 8 + cq)     * WS_STR + n * 8 + r];
                uint32_t b1 = Ws[(ks * 8 + cq + 4) * WS_STR + n * 8 + r];
                mma_tf32(acc[n], a0, a1, a2, a3, b0, b1);
            }
        }
    }

    // epilogue
    const int tr0 = m0 + w16 + r;
    #pragma unroll
    for (int n = 0; n < 24; n++) {
        int which = n >> 3;
        int col   = (n * 8) & 63;
        float* op = (which == 0) ? g_q : (which == 1) ? g_k : g_v;
        *(float2*)(op + (size_t)tr0       * H + col + 2 * cq) = make_float2(acc[n][0], acc[n][1]);
        *(float2*)(op + (size_t)(tr0 + 8) * H + col + 2 * cq) = make_float2(acc[n][2], acc[n][3]);
    }
}

// ===========================================================================
// Kernel B: causal flash attention with mma.sync tf32 (FA2 style).
// Round-8 scheduling: 128 blocks (4 batches x 32 pairs), 128 threads (4 warps),
// halves qt = pair and 63-pair -> uniform 65 key-tiles per block.
// CHANGE vs round 8: K stored in NATURAL [key][dim] layout (no transpose).
// The mma ".col" B operand of S = Q*K^T is K^T column-major == K row-major,
// so B fragments read directly: b0 = Ks[(n*8+r)*KS_STR + ks*8+cq].
// This removes the 16-way bank-conflicted scalar transpose stores.
// ===========================================================================
#define QS_STR 68
#define KS_STR 68
#define VS_STR 72
#define PS_STR 68
#define AT_SMEM_WORDS (64*QS_STR + 64*KS_STR + 64*VS_STR + 4*16*PS_STR)

__global__ __launch_bounds__(128, 1) void attn_mma_kernel(float* __restrict__ out)
{
    extern __shared__ uint32_t sm[];
    uint32_t* Qs = sm;                          // [64][QS_STR] tf32 (scaled)
    uint32_t* Ks = Qs + 64 * QS_STR;            // [64 key][KS_STR dim] tf32, natural
    uint32_t* Vs = Ks + 64 * KS_STR;            // [64 key][VS_STR dim] tf32, natural
    uint32_t* Ps = Vs + 64 * VS_STR;            // per-warp [16][PS_STR] tf32

    const int b    = blockIdx.x >> 5;
    const int pair = blockIdx.x & 31;
    const int tid  = threadIdx.x;
    const int wid  = tid >> 5;
    const int lane = tid & 31;
    const int r    = lane >> 2;                 // 0..7
    const int cq   = lane & 3;                  // 0..3
    const int w16  = wid * 16;
    uint32_t* Pw   = Ps + wid * 16 * PS_STR;

    const float* __restrict__ qg = g_q + (size_t)b * T * H;
    const float* __restrict__ kg = g_k + (size_t)b * T * H;
    const float* __restrict__ vg = g_v + (size_t)b * T * H;

    #pragma unroll 1
    for (int half = 0; half < 2; half++) {
        const int qt = (half == 0) ? pair : (63 - pair);
        const int q0 = qt * 64;
        const int ntiles = qt + 1;

        __syncthreads();
        // load Q tile: 64 rows x 64 cols = 1024 float4 (scaled, tf32)
        #pragma unroll
        for (int i = 0; i < 8; i++) {
            int f   = i * 128 + tid;            // 0..1023 float4
            int row = f >> 4;                   // 0..63
            int c4  = (f & 15) * 4;
            float4 v = *(const float4*)(qg + (size_t)(q0 + row) * H + c4);
            *(uint4*)&Qs[row * QS_STR + c4] = make_uint4(
                f32_to_tf32(v.x * SCALE), f32_to_tf32(v.y * SCALE),
                f32_to_tf32(v.z * SCALE), f32_to_tf32(v.w * SCALE));
        }
        __syncthreads();

        // Q A-fragments: persistent in registers
        uint32_t qa[8][4];
        #pragma unroll
        for (int ks = 0; ks < 8; ks++) {
            qa[ks][0] = Qs[(w16 + r)     * QS_STR + ks * 8 + cq];
            qa[ks][1] = Qs[(w16 + r + 8) * QS_STR + ks * 8 + cq];
            qa[ks][2] = Qs[(w16 + r)     * QS_STR + ks * 8 + cq + 4];
            qa[ks][3] = Qs[(w16 + r + 8) * QS_STR + ks * 8 + cq + 4];
        }

        float O[8][4];
        #pragma unroll
        for (int n = 0; n < 8; n++)
            #pragma unroll
            for (int j = 0; j < 4; j++) O[n][j] = 0.f;
        float m0h = -1e30f, m1h = -1e30f, l0 = 0.f, l1 = 0.f;

        const int tr0g = q0 + w16 + r;
        const int tr1g = tr0g + 8;

        for (int tile = 0; tile < ntiles; tile++) {
            const int s0 = tile * 64;

            __syncthreads();   // everyone done reading Ks/Vs of previous tile
            // K and V tiles in NATURAL layout: plain uint4 stores, no transpose
            #pragma unroll
            for (int i = 0; i < 8; i++) {
                int f   = i * 128 + tid;        // 1024 float4
                int row = f >> 4;               // key index 0..63
                int c4  = (f & 15) * 4;         // dim base
                float4 kv = *(const float4*)(kg + (size_t)(s0 + row) * H + c4);
                *(uint4*)&Ks[row * KS_STR + c4] = make_uint4(
                    f32_to_tf32(kv.x), f32_to_tf32(kv.y),
                    f32_to_tf32(kv.z), f32_to_tf32(kv.w));
                float4 vv = *(const float4*)(vg + (size_t)(s0 + row) * H + c4);
                *(uint4*)&Vs[row * VS_STR + c4] = make_uint4(
                    f32_to_tf32(vv.x), f32_to_tf32(vv.y),
                    f32_to_tf32(vv.z), f32_to_tf32(vv.w));
            }
            __syncthreads();

            // ---- S = Q * K^T ----
            float S[8][4];
            #pragma unroll
            for (int n = 0; n < 8; n++) {
                #pragma unroll
                for (int j = 0; j < 4; j++) S[n][j] = 0.f;
            }
            #pragma unroll
            for (int n = 0; n < 8; n++) {
                const uint32_t* krow = &Ks[(n * 8 + r) * KS_STR + cq];
                #pragma unroll
                for (int ks = 0; ks < 8; ks++) {
                    uint32_t b0 = krow[ks * 8];
                    uint32_t b1 = krow[ks * 8 + 4];
                    mma_tf32(S[n], qa[ks][0], qa[ks][1], qa[ks][2], qa[ks][3], b0, b1);
                }
            }

            // ---- causal mask on diagonal tile ----
            if (tile == qt) {
                #pragma unroll
                for (int n = 0; n < 8; n++) {
                    int col0 = s0 + n * 8 + 2 * cq;
                    int col1 = col0 + 1;
                    if (col0 > tr0g) S[n][0] = -1e30f;
                    if (col1 > tr0g) S[n][1] = -1e30f;
                    if (col0 > tr1g) S[n][2] = -1e30f;
                    if (col1 > tr1g) S[n][3] = -1e30f;
                }
            }

            // ---- online softmax (rows split: [0,1] row r; [2,3] row r+8) ----
            float mx0 = -1e30f, mx1 = -1e30f;
            #pragma unroll
            for (int n = 0; n < 8; n++) {
                mx0 = fmaxf(mx0, fmaxf(S[n][0], S[n][1]));
                mx1 = fmaxf(mx1, fmaxf(S[n][2], S[n][3]));
            }
            mx0 = fmaxf(mx0, __shfl_xor_sync(0xffffffffu, mx0, 1));
            mx0 = fmaxf(mx0, __shfl_xor_sync(0xffffffffu, mx0, 2));
            mx1 = fmaxf(mx1, __shfl_xor_sync(0xffffffffu, mx1, 1));
            mx1 = fmaxf(mx1, __shfl_xor_sync(0xffffffffu, mx1, 2));

            float mn0 = fmaxf(m0h, mx0);
            float mn1 = fmaxf(m1h, mx1);
            float corr0 = __expf(m0h - mn0);
            float corr1 = __expf(m1h - mn1);
            m0h = mn0; m1h = mn1;

            float rs0 = 0.f, rs1 = 0.f;
            #pragma unroll
            for (int n = 0; n < 8; n++) {
                uint32_t p00 = f32_to_tf32(__expf(S[n][0] - mn0));
                uint32_t p01 = f32_to_tf32(__expf(S[n][1] - mn0));
                uint32_t p10 = f32_to_tf32(__expf(S[n][2] - mn1));
                uint32_t p11 = f32_to_tf32(__expf(S[n][3] - mn1));
                rs0 += __uint_as_float(p00) + __uint_as_float(p01);
                rs1 += __uint_as_float(p10) + __uint_as_float(p11);
                *(uint2*)&Pw[r       * PS_STR + n * 8 + 2 * cq] = make_uint2(p00, p01);
                *(uint2*)&Pw[(r + 8) * PS_STR + n * 8 + 2 * cq] = make_uint2(p10, p11);
            }
            rs0 += __shfl_xor_sync(0xffffffffu, rs0, 1);
            rs0 += __shfl_xor_sync(0xffffffffu, rs0, 2);
            rs1 += __shfl_xor_sync(0xffffffffu, rs1, 1);
            rs1 += __shfl_xor_sync(0xffffffffu, rs1, 2);
            l0 = l0 * corr0 + rs0;
            l1 = l1 * corr1 + rs1;

            #pragma unroll
            for (int n = 0; n < 8; n++) {
                O[n][0] *= corr0; O[n][1] *= corr0;
                O[n][2] *= corr1; O[n][3] *= corr1;
            }
            __syncwarp();

            // ---- O += P * V  (V natural: b0 = Vs[(ks*8+cq)*VS_STR + n*8+r]) ----
            #pragma unroll
            for (int ks = 0; ks < 8; ks++) {
                uint32_t a0 = Pw[r       * PS_STR + ks * 8 + cq];
                uint32_t a1 = Pw[(r + 8) * PS_STR + ks * 8 + cq];
                uint32_t a2 = Pw[r       * PS_STR + ks * 8 + cq + 4];
                uint32_t a3 = Pw[(r + 8) * PS_STR + ks * 8 + cq + 4];
                #pragma unroll
                for (int n = 0; n < 8; n++) {
                    uint32_t b0 = Vs[(ks * 8 + cq)     * VS_STR + n * 8 + r];
                    uint32_t b1 = Vs[(ks * 8 + cq + 4) * VS_STR + n * 8 + r];
                    mma_tf32(O[n], a0, a1, a2, a3, b0, b1);
                }
            }
            __syncwarp();
        }

        // ---- epilogue ----
        float inv0 = 1.0f / l0;
        float inv1 = 1.0f / l1;
        float* o0 = out + ((size_t)b * T + tr0g) * H;
        float* o1 = out + ((size_t)b * T + tr1g) * H;
        #pragma unroll
        for (int n = 0; n < 8; n++) {
            *(float2*)(o0 + n * 8 + 2 * cq) = make_float2(O[n][0] * inv0, O[n][1] * inv0);
            *(float2*)(o1 + n * 8 + 2 * cq) = make_float2(O[n][2] * inv1, O[n][3] * inv1);
        }
    }
}

// ---------------------------------------------------------------------------
extern "C" void kernel_launch(void* const* d_in, const int* in_sizes, int n_in,
                              void* d_out, int out_size)
{
    const float* x  = (const float*)d_in[0];
    const float* Wq = (const float*)d_in[1];
    const float* Wk = (const float*)d_in[2];
    const float* Wv = (const float*)d_in[3];
    float* out = (float*)d_out;

    static int attr_set = 0;
    const int pj_smem = PJ_SMEM_WORDS * 4;
    const int at_smem = AT_SMEM_WORDS * 4;
    if (!attr_set) {
        cudaFuncSetAttribute(proj_mma_kernel,
                             cudaFuncAttributeMaxDynamicSharedMemorySize, pj_smem);
        cudaFuncSetAttribute(attn_mma_kernel,
                             cudaFuncAttributeMaxDynamicSharedMemorySize, at_smem);
        attr_set = 1;
    }

    proj_mma_kernel<<<TOTROWS / 128, 256, pj_smem>>>(x, Wq, Wk, Wv);
    attn_mma_kernel<<<BATCH * 32, 128, at_smem>>>(out);
}

// round 14
// speedup vs baseline: 1.7877x; 1.1260x over previous
#include <cuda_runtime.h>
#include <math.h>
#include <stdint.h>

// Problem constants
#define BATCH 4
#define T     4096
#define C     1024
#define H     64
#define TOTROWS (BATCH * T)          // 16384
#define SCALE 0.03125f               // C^-0.5 = 1/32

// Scratch for projected q, k, v
__device__ float g_q[TOTROWS * H];
__device__ float g_k[TOTROWS * H];
__device__ float g_v[TOTROWS * H];

// ---------------------------------------------------------------------------
// tf32 / cp.async helpers
// ---------------------------------------------------------------------------
__device__ __forceinline__ uint32_t f32_to_tf32(float x) {
    uint32_t y;
    asm("cvt.rna.tf32.f32 %0, %1;" : "=r"(y) : "f"(x));
    return y;
}

__device__ __forceinline__ uint32_t smem_u32(const void* p) {
    uint32_t a;
    asm("{ .reg .u64 t; cvta.to.shared.u64 t, %1; cvt.u32.u64 %0, t; }" : "=r"(a) : "l"(p));
    return a;
}
__device__ __forceinline__ void cp_async16(uint32_t dst, const void* src) {
    asm volatile("cp.async.cg.shared.global [%0], [%1], 16;" :: "r"(dst), "l"(src));
}
#define CP_COMMIT() asm volatile("cp.async.commit_group;" ::: "memory")
#define CP_WAIT0()  asm volatile("cp.async.wait_group 0;" ::: "memory")

// D = A(16x8,row) * B(8x8,col) + D ; tf32 inputs, fp32 accum
__device__ __forceinline__ void mma_tf32(float c[4],
                                         uint32_t a0, uint32_t a1, uint32_t a2, uint32_t a3,
                                         uint32_t b0, uint32_t b1) {
    asm volatile(
        "mma.sync.aligned.m16n8k8.row.col.f32.tf32.tf32.f32 "
        "{%0,%1,%2,%3}, {%4,%5,%6,%7}, {%8,%9}, {%0,%1,%2,%3};"
        : "+f"(c[0]), "+f"(c[1]), "+f"(c[2]), "+f"(c[3])
        : "r"(a0), "r"(a1), "r"(a2), "r"(a3), "r"(b0), "r"(b1));
}

// ===========================================================================
// Kernel A: fused QKV projection with mma.sync tf32 (validated in round 7).
// ===========================================================================
#define XS_STR 68     // uint32 stride
#define WS_STR 200    // uint32 stride
#define PJ_SMEM_WORDS (128 * XS_STR + 64 * WS_STR)

__global__ __launch_bounds__(256, 1) void proj_mma_kernel(
    const float* __restrict__ x,
    const float* __restrict__ Wq,
    const float* __restrict__ Wk,
    const float* __restrict__ Wv)
{
    extern __shared__ uint32_t smw[];
    uint32_t* Xs = smw;                   // [128][XS_STR]
    uint32_t* Ws = smw + 128 * XS_STR;    // [64][WS_STR], cols 0..191 used

    const int tid  = threadIdx.x;
    const int wid  = tid >> 5;
    const int lane = tid & 31;
    const int r    = lane >> 2;           // 0..7
    const int cq   = lane & 3;            // 0..3
    const int w16  = wid * 16;
    const int m0   = blockIdx.x * 128;

    float acc[24][4];
    #pragma unroll
    for (int n = 0; n < 24; n++)
        #pragma unroll
        for (int j = 0; j < 4; j++) acc[n][j] = 0.f;

    for (int ch = 0; ch < 16; ch++) {
        const int k0 = ch * 64;
        __syncthreads();

        #pragma unroll
        for (int i = 0; i < 8; i++) {
            int f   = i * 256 + tid;            // 0..2047 float4
            int row = f >> 4;
            int c4  = (f & 15) * 4;
            float4 v = *(const float4*)(x + (size_t)(m0 + row) * C + k0 + c4);
            *(uint4*)&Xs[row * XS_STR + c4] = make_uint4(
                f32_to_tf32(v.x), f32_to_tf32(v.y), f32_to_tf32(v.z), f32_to_tf32(v.w));
        }
        #pragma unroll
        for (int i = 0; i < 12; i++) {
            int f  = i * 256 + tid;             // 0..3071 float4
            int w  = f >> 10;                   // 0..2
            int rr = f & 1023;
            int kk = rr >> 4;                   // 0..63
            int n4 = (rr & 15) * 4;             // 0..60
            const float* Wp = (w == 0) ? Wq : (w == 1) ? Wk : Wv;
            float4 v = *(const float4*)(Wp + (size_t)(k0 + kk) * H + n4);
            *(uint4*)&Ws[kk * WS_STR + w * 64 + n4] = make_uint4(
                f32_to_tf32(v.x), f32_to_tf32(v.y), f32_to_tf32(v.z), f32_to_tf32(v.w));
        }
        __syncthreads();

        #pragma unroll
        for (int ks = 0; ks < 8; ks++) {
            uint32_t a0 = Xs[(w16 + r)     * XS_STR + ks * 8 + cq];
            uint32_t a1 = Xs[(w16 + r + 8) * XS_STR + ks * 8 + cq];
            uint32_t a2 = Xs[(w16 + r)     * XS_STR + ks * 8 + cq + 4];
            uint32_t a3 = Xs[(w16 + r + 8) * XS_STR + ks * 8 + cq + 4];
            #pragma unroll
            for (int n = 0; n < 24; n++) {
                uint32_t b0 = Ws[(ks * 8 + cq)     * WS_STR + n * 8 + r];
                uint32_t b1 = Ws[(ks * 8 + cq + 4) * WS_STR + n * 8 + r];
                mma_tf32(acc[n], a0, a1, a2, a3, b0, b1);
            }
        }
    }

    const int tr0 = m0 + w16 + r;
    #pragma unroll
    for (int n = 0; n < 24; n++) {
        int which = n >> 3;
        int col   = (n * 8) & 63;
        float* op = (which == 0) ? g_q : (which == 1) ? g_k : g_v;
        *(float2*)(op + (size_t)tr0       * H + col + 2 * cq) = make_float2(acc[n][0], acc[n][1]);
        *(float2*)(op + (size_t)(tr0 + 8) * H + col + 2 * cq) = make_float2(acc[n][2], acc[n][3]);
    }
}

// ===========================================================================
// Kernel B: causal flash attention, mma.sync tf32, cp.async double-buffered.
// 128 blocks (4 batches x 32 pairs), 128 threads (4 warps), halves qt = pair
// and 63-pair -> uniform 65 key-tiles per block.
// K/V tiles: raw fp32 bits via cp.async.cg (tensor core truncates to tf32),
// double-buffered; tile i+1 fetch overlaps tile i compute.
// ===========================================================================
#define QS_STR 68
#define KS_STR 68
#define VS_STR 72
#define PS_STR 68
#define KV_BUF_WORDS (64 * KS_STR + 64 * VS_STR)
#define AT_SMEM_WORDS (64*QS_STR + 2*KV_BUF_WORDS + 4*16*PS_STR)

__global__ __launch_bounds__(128, 1) void attn_mma_kernel(float* __restrict__ out)
{
    extern __shared__ uint32_t sm[];
    uint32_t* Qs   = sm;                         // [64][QS_STR] tf32 (scaled)
    uint32_t* KV0  = Qs + 64 * QS_STR;           // buf0: K then V
    uint32_t* KV1  = KV0 + KV_BUF_WORDS;         // buf1
    uint32_t* Ps   = KV1 + KV_BUF_WORDS;         // per-warp [16][PS_STR]

    const int b    = blockIdx.x >> 5;
    const int pair = blockIdx.x & 31;
    const int tid  = threadIdx.x;
    const int wid  = tid >> 5;
    const int lane = tid & 31;
    const int r    = lane >> 2;                  // 0..7
    const int cq   = lane & 3;                   // 0..3
    const int w16  = wid * 16;
    uint32_t* Pw   = Ps + wid * 16 * PS_STR;

    const float* __restrict__ qg = g_q + (size_t)b * T * H;
    const float* __restrict__ kg = g_k + (size_t)b * T * H;
    const float* __restrict__ vg = g_v + (size_t)b * T * H;

    // per-thread cp.async coordinates: f = i*128 + tid, row = f>>4, c4 = (f&15)*4
    const int cp_row = tid >> 4;                 // base row for i=0 (rows step by 8)
    const int cp_c4  = (tid & 15) * 4;

    #pragma unroll 1
    for (int half = 0; half < 2; half++) {
        const int qt = (half == 0) ? pair : (63 - pair);
        const int q0 = qt * 64;
        const int ntiles = qt + 1;

        __syncthreads();    // previous half done with all buffers

        // ---- prefetch tile 0 into buf0 ----
        {
            uint32_t kdst = smem_u32(&KV0[cp_row * KS_STR + cp_c4]);
            uint32_t vdst = smem_u32(&KV0[64 * KS_STR + cp_row * VS_STR + cp_c4]);
            const float* ksrc = kg + (size_t)cp_row * H + cp_c4;
            const float* vsrc = vg + (size_t)cp_row * H + cp_c4;
            #pragma unroll
            for (int i = 0; i < 8; i++) {
                cp_async16(kdst + i * 8 * KS_STR * 4, ksrc + (size_t)i * 8 * H);
                cp_async16(vdst + i * 8 * VS_STR * 4, vsrc + (size_t)i * 8 * H);
            }
            CP_COMMIT();
        }

        // ---- load Q tile (scaled, rna tf32) while prefetch flies ----
        #pragma unroll
        for (int i = 0; i < 8; i++) {
            int f   = i * 128 + tid;
            int row = f >> 4;
            int c4  = (f & 15) * 4;
            float4 v = *(const float4*)(qg + (size_t)(q0 + row) * H + c4);
            *(uint4*)&Qs[row * QS_STR + c4] = make_uint4(
                f32_to_tf32(v.x * SCALE), f32_to_tf32(v.y * SCALE),
                f32_to_tf32(v.z * SCALE), f32_to_tf32(v.w * SCALE));
        }
        __syncthreads();

        // Q A-fragments: persistent in registers
        uint32_t qa[8][4];
        #pragma unroll
        for (int ks = 0; ks < 8; ks++) {
            qa[ks][0] = Qs[(w16 + r)     * QS_STR + ks * 8 + cq];
            qa[ks][1] = Qs[(w16 + r + 8) * QS_STR + ks * 8 + cq];
            qa[ks][2] = Qs[(w16 + r)     * QS_STR + ks * 8 + cq + 4];
            qa[ks][3] = Qs[(w16 + r + 8) * QS_STR + ks * 8 + cq + 4];
        }

        float O[8][4];
        #pragma unroll
        for (int n = 0; n < 8; n++)
            #pragma unroll
            for (int j = 0; j < 4; j++) O[n][j] = 0.f;
        float m0h = -1e30f, m1h = -1e30f, l0 = 0.f, l1 = 0.f;

        const int tr0g = q0 + w16 + r;
        const int tr1g = tr0g + 8;

        for (int tile = 0; tile < ntiles; tile++) {
            uint32_t* KV  = (tile & 1) ? KV1 : KV0;
            uint32_t* Ks  = KV;
            uint32_t* Vs  = KV + 64 * KS_STR;

            CP_WAIT0();          // this tile's K/V landed
            __syncthreads();     // visible to all warps; prev compute done everywhere

            // ---- prefetch next tile into the other buffer ----
            if (tile + 1 < ntiles) {
                uint32_t* KVn = (tile & 1) ? KV0 : KV1;
                const int sn = (tile + 1) * 64;
                uint32_t kdst = smem_u32(&KVn[cp_row * KS_STR + cp_c4]);
                uint32_t vdst = smem_u32(&KVn[64 * KS_STR + cp_row * VS_STR + cp_c4]);
                const float* ksrc = kg + (size_t)(sn + cp_row) * H + cp_c4;
                const float* vsrc = vg + (size_t)(sn + cp_row) * H + cp_c4;
                #pragma unroll
                for (int i = 0; i < 8; i++) {
                    cp_async16(kdst + i * 8 * KS_STR * 4, ksrc + (size_t)i * 8 * H);
                    cp_async16(vdst + i * 8 * VS_STR * 4, vsrc + (size_t)i * 8 * H);
                }
                CP_COMMIT();
            }

            const int s0 = tile * 64;

            // ---- S = Q * K^T (K natural layout; B-frag = direct reads) ----
            float S[8][4];
            #pragma unroll
            for (int n = 0; n < 8; n++) {
                #pragma unroll
                for (int j = 0; j < 4; j++) S[n][j] = 0.f;
            }
            #pragma unroll
            for (int n = 0; n < 8; n++) {
                const uint32_t* krow = &Ks[(n * 8 + r) * KS_STR + cq];
                #pragma unroll
                for (int ks = 0; ks < 8; ks++) {
                    uint32_t b0 = krow[ks * 8];
                    uint32_t b1 = krow[ks * 8 + 4];
                    mma_tf32(S[n], qa[ks][0], qa[ks][1], qa[ks][2], qa[ks][3], b0, b1);
                }
            }

            // ---- causal mask on diagonal tile ----
            if (tile == qt) {
                #pragma unroll
                for (int n = 0; n < 8; n++) {
                    int col0 = s0 + n * 8 + 2 * cq;
                    int col1 = col0 + 1;
                    if (col0 > tr0g) S[n][0] = -1e30f;
                    if (col1 > tr0g) S[n][1] = -1e30f;
                    if (col0 > tr1g) S[n][2] = -1e30f;
                    if (col1 > tr1g) S[n][3] = -1e30f;
                }
            }

            // ---- online softmax ----
            float mx0 = -1e30f, mx1 = -1e30f;
            #pragma unroll
            for (int n = 0; n < 8; n++) {
                mx0 = fmaxf(mx0, fmaxf(S[n][0], S[n][1]));
                mx1 = fmaxf(mx1, fmaxf(S[n][2], S[n][3]));
            }
            mx0 = fmaxf(mx0, __shfl_xor_sync(0xffffffffu, mx0, 1));
            mx0 = fmaxf(mx0, __shfl_xor_sync(0xffffffffu, mx0, 2));
            mx1 = fmaxf(mx1, __shfl_xor_sync(0xffffffffu, mx1, 1));
            mx1 = fmaxf(mx1, __shfl_xor_sync(0xffffffffu, mx1, 2));

            float mn0 = fmaxf(m0h, mx0);
            float mn1 = fmaxf(m1h, mx1);
            float corr0 = __expf(m0h - mn0);
            float corr1 = __expf(m1h - mn1);
            m0h = mn0; m1h = mn1;

            float rs0 = 0.f, rs1 = 0.f;
            #pragma unroll
            for (int n = 0; n < 8; n++) {
                uint32_t p00 = f32_to_tf32(__expf(S[n][0] - mn0));
                uint32_t p01 = f32_to_tf32(__expf(S[n][1] - mn0));
                uint32_t p10 = f32_to_tf32(__expf(S[n][2] - mn1));
                uint32_t p11 = f32_to_tf32(__expf(S[n][3] - mn1));
                rs0 += __uint_as_float(p00) + __uint_as_float(p01);
                rs1 += __uint_as_float(p10) + __uint_as_float(p11);
                *(uint2*)&Pw[r       * PS_STR + n * 8 + 2 * cq] = make_uint2(p00, p01);
                *(uint2*)&Pw[(r + 8) * PS_STR + n * 8 + 2 * cq] = make_uint2(p10, p11);
            }
            rs0 += __shfl_xor_sync(0xffffffffu, rs0, 1);
            rs0 += __shfl_xor_sync(0xffffffffu, rs0, 2);
            rs1 += __shfl_xor_sync(0xffffffffu, rs1, 1);
            rs1 += __shfl_xor_sync(0xffffffffu, rs1, 2);
            l0 = l0 * corr0 + rs0;
            l1 = l1 * corr1 + rs1;

            #pragma unroll
            for (int n = 0; n < 8; n++) {
                O[n][0] *= corr0; O[n][1] *= corr0;
                O[n][2] *= corr1; O[n][3] *= corr1;
            }
            __syncwarp();

            // ---- O += P * V ----
            #pragma unroll
            for (int ks = 0; ks < 8; ks++) {
                uint32_t a0 = Pw[r       * PS_STR + ks * 8 + cq];
                uint32_t a1 = Pw[(r + 8) * PS_STR + ks * 8 + cq];
                uint32_t a2 = Pw[r       * PS_STR + ks * 8 + cq + 4];
                uint32_t a3 = Pw[(r + 8) * PS_STR + ks * 8 + cq + 4];
                #pragma unroll
                for (int n = 0; n < 8; n++) {
                    uint32_t b0 = Vs[(ks * 8 + cq)     * VS_STR + n * 8 + r];
                    uint32_t b1 = Vs[(ks * 8 + cq + 4) * VS_STR + n * 8 + r];
                    mma_tf32(O[n], a0, a1, a2, a3, b0, b1);
                }
            }
            __syncwarp();
        }

        // ---- epilogue ----
        float inv0 = 1.0f / l0;
        float inv1 = 1.0f / l1;
        float* o0 = out + ((size_t)b * T + tr0g) * H;
        float* o1 = out + ((size_t)b * T + tr1g) * H;
        #pragma unroll
        for (int n = 0; n < 8; n++) {
            *(float2*)(o0 + n * 8 + 2 * cq) = make_float2(O[n][0] * inv0, O[n][1] * inv0);
            *(float2*)(o1 + n * 8 + 2 * cq) = make_float2(O[n][2] * inv1, O[n][3] * inv1);
        }
    }
}

// ---------------------------------------------------------------------------
extern "C" void kernel_launch(void* const* d_in, const int* in_sizes, int n_in,
                              void* d_out, int out_size)
{
    const float* x  = (const float*)d_in[0];
    const float* Wq = (const float*)d_in[1];
    const float* Wk = (const float*)d_in[2];
    const float* Wv = (const float*)d_in[3];
    float* out = (float*)d_out;

    static int attr_set = 0;
    const int pj_smem = PJ_SMEM_WORDS * 4;
    const int at_smem = AT_SMEM_WORDS * 4;
    if (!attr_set) {
        cudaFuncSetAttribute(proj_mma_kernel,
                             cudaFuncAttributeMaxDynamicSharedMemorySize, pj_smem);
        cudaFuncSetAttribute(attn_mma_kernel,
                             cudaFuncAttributeMaxDynamicSharedMemorySize, at_smem);
        attr_set = 1;
    }

    proj_mma_kernel<<<TOTROWS / 128, 256, pj_smem>>>(x, Wq, Wk, Wv);
    attn_mma_kernel<<<BATCH * 32, 128, at_smem>>>(out);
}

// round 15
// speedup vs baseline: 1.8613x; 1.0412x over previous
#include <cuda_runtime.h>
#include <math.h>
#include <stdint.h>

// Problem constants
#define BATCH 4
#define T     4096
#define C     1024
#define H     64
#define TOTROWS (BATCH * T)          // 16384
#define SCALE 0.03125f               // C^-0.5 = 1/32

// Scratch for projected q, k, v
__device__ float g_q[TOTROWS * H];
__device__ float g_k[TOTROWS * H];
__device__ float g_v[TOTROWS * H];

// ---------------------------------------------------------------------------
// tf32 / cp.async helpers
// ---------------------------------------------------------------------------
__device__ __forceinline__ uint32_t f32_to_tf32(float x) {
    uint32_t y;
    asm("cvt.rna.tf32.f32 %0, %1;" : "=r"(y) : "f"(x));
    return y;
}
__device__ __forceinline__ uint32_t bits_to_tf32(uint32_t raw) {
    return f32_to_tf32(__uint_as_float(raw));
}

__device__ __forceinline__ uint32_t smem_u32(const void* p) {
    uint32_t a;
    asm("{ .reg .u64 t; cvta.to.shared.u64 t, %1; cvt.u32.u64 %0, t; }" : "=r"(a) : "l"(p));
    return a;
}
__device__ __forceinline__ void cp_async16(uint32_t dst, const void* src) {
    asm volatile("cp.async.cg.shared.global [%0], [%1], 16;" :: "r"(dst), "l"(src));
}
#define CP_COMMIT() asm volatile("cp.async.commit_group;" ::: "memory")
#define CP_WAIT0()  asm volatile("cp.async.wait_group 0;" ::: "memory")

// D = A(16x8,row) * B(8x8,col) + D ; tf32 inputs, fp32 accum
__device__ __forceinline__ void mma_tf32(float c[4],
                                         uint32_t a0, uint32_t a1, uint32_t a2, uint32_t a3,
                                         uint32_t b0, uint32_t b1) {
    asm volatile(
        "mma.sync.aligned.m16n8k8.row.col.f32.tf32.tf32.f32 "
        "{%0,%1,%2,%3}, {%4,%5,%6,%7}, {%8,%9}, {%0,%1,%2,%3};"
        : "+f"(c[0]), "+f"(c[1]), "+f"(c[2]), "+f"(c[3])
        : "r"(a0), "r"(a1), "r"(a2), "r"(a3), "r"(b0), "r"(b1));
}

// ===========================================================================
// Kernel A: fused QKV projection, cp.async double-buffered, 2x4 warp tiling.
// 256 threads = 8 warps as (2 m-halves x 4 n-quarters): warp owns 64 rows x
// 48 cols (4 m-tiles x 6 n-tiles). Chunks land raw (fp32 bits) via cp.async;
// fragments are cvt.rna'd in registers -> full rna precision, overlapped loads.
// ===========================================================================
#define XS_STR 68     // uint32 stride (272B, 16B-aligned)
#define WS_STR 200    // uint32 stride (800B, 16B-aligned)
#define X_BUF_WORDS (128 * XS_STR)
#define W_BUF_WORDS (64 * WS_STR)
#define PJ_SMEM_WORDS (2 * X_BUF_WORDS + 2 * W_BUF_WORDS)

__global__ __launch_bounds__(256, 1) void proj_mma_kernel(
    const float* __restrict__ x,
    const float* __restrict__ Wq,
    const float* __restrict__ Wk,
    const float* __restrict__ Wv)
{
    extern __shared__ uint32_t smw[];
    uint32_t* Xb[2] = { smw, smw + X_BUF_WORDS };
    uint32_t* Wb[2] = { smw + 2 * X_BUF_WORDS, smw + 2 * X_BUF_WORDS + W_BUF_WORDS };

    const int tid  = threadIdx.x;
    const int wid  = tid >> 5;
    const int lane = tid & 31;
    const int r    = lane >> 2;           // 0..7
    const int cq   = lane & 3;            // 0..3
    const int mrow = (wid & 1) * 64;      // warp m-half
    const int ncol = (wid >> 1) * 48;     // warp n-quarter (48 cols)
    const int m0   = blockIdx.x * 128;

    // prefetch helper coordinates
    auto prefetch = [&](int ch, int buf) {
        const int k0 = ch * 64;
        // x chunk: 128 rows x 64 cols = 2048 float4
        uint32_t xdst0 = smem_u32(&Xb[buf][(tid >> 4) * XS_STR + (tid & 15) * 4]);
        const float* xsrc0 = x + (size_t)(m0 + (tid >> 4)) * C + k0 + (tid & 15) * 4;
        #pragma unroll
        for (int i = 0; i < 8; i++)   // rows step by 16
            cp_async16(xdst0 + i * 16 * XS_STR * 4, xsrc0 + (size_t)i * 16 * C);
        // W chunk: 64 k x 192 n = 3072 float4
        #pragma unroll
        for (int i = 0; i < 12; i++) {
            int f  = i * 256 + tid;
            int w  = f >> 10;
            int rr = f & 1023;
            int kk = rr >> 4;
            int n4 = (rr & 15) * 4;
            const float* Wp = (w == 0) ? Wq : (w == 1) ? Wk : Wv;
            cp_async16(smem_u32(&Wb[buf][kk * WS_STR + w * 64 + n4]),
                       Wp + (size_t)(k0 + kk) * H + n4);
        }
        CP_COMMIT();
    };

    float acc[4][6][4];
    #pragma unroll
    for (int mt = 0; mt < 4; mt++)
        #pragma unroll
        for (int nt = 0; nt < 6; nt++)
            #pragma unroll
            for (int j = 0; j < 4; j++) acc[mt][nt][j] = 0.f;

    prefetch(0, 0);

    for (int ch = 0; ch < 16; ch++) {
        const int buf = ch & 1;
        CP_WAIT0();
        __syncthreads();
        if (ch + 1 < 16) prefetch(ch + 1, buf ^ 1);

        const uint32_t* Xs = Xb[buf];
        const uint32_t* Ws = Wb[buf];

        #pragma unroll
        for (int ks = 0; ks < 8; ks++) {
            uint32_t a[4][4];
            #pragma unroll
            for (int mt = 0; mt < 4; mt++) {
                int rowb = (mrow + mt * 16 + r) * XS_STR + ks * 8 + cq;
                a[mt][0] = bits_to_tf32(Xs[rowb]);
                a[mt][1] = bits_to_tf32(Xs[rowb + 8 * XS_STR]);
                a[mt][2] = bits_to_tf32(Xs[rowb + 4]);
                a[mt][3] = bits_to_tf32(Xs[rowb + 8 * XS_STR + 4]);
            }
            uint32_t bb[6][2];
            #pragma unroll
            for (int nt = 0; nt < 6; nt++) {
                int cb = ncol + nt * 8 + r;
                bb[nt][0] = bits_to_tf32(Ws[(ks * 8 + cq)     * WS_STR + cb]);
                bb[nt][1] = bits_to_tf32(Ws[(ks * 8 + cq + 4) * WS_STR + cb]);
            }
            #pragma unroll
            for (int mt = 0; mt < 4; mt++)
                #pragma unroll
                for (int nt = 0; nt < 6; nt++)
                    mma_tf32(acc[mt][nt], a[mt][0], a[mt][1], a[mt][2], a[mt][3],
                             bb[nt][0], bb[nt][1]);
        }
        __syncthreads();
    }

    // epilogue
    #pragma unroll
    for (int mt = 0; mt < 4; mt++) {
        const int tr = m0 + mrow + mt * 16 + r;
        #pragma unroll
        for (int nt = 0; nt < 6; nt++) {
            int gc    = ncol + nt * 8;          // global output col 0..184 (mult of 8)
            int which = gc >> 6;
            int cb    = (gc & 63) + 2 * cq;
            float* op = (which == 0) ? g_q : (which == 1) ? g_k : g_v;
            *(float2*)(op + (size_t)tr       * H + cb) = make_float2(acc[mt][nt][0], acc[mt][nt][1]);
            *(float2*)(op + (size_t)(tr + 8) * H + cb) = make_float2(acc[mt][nt][2], acc[mt][nt][3]);
        }
    }
}

// ===========================================================================
// Kernel B: causal flash attention, mma.sync tf32, cp.async double-buffered.
// (Unchanged from round 14 — 96 us, validated.)
// ===========================================================================
#define QS_STR 68
#define KS_STR 68
#define VS_STR 72
#define PS_STR 68
#define KV_BUF_WORDS (64 * KS_STR + 64 * VS_STR)
#define AT_SMEM_WORDS (64*QS_STR + 2*KV_BUF_WORDS + 4*16*PS_STR)

__global__ __launch_bounds__(128, 1) void attn_mma_kernel(float* __restrict__ out)
{
    extern __shared__ uint32_t sm[];
    uint32_t* Qs   = sm;                         // [64][QS_STR] tf32 (scaled)
    uint32_t* KV0  = Qs + 64 * QS_STR;           // buf0: K then V
    uint32_t* KV1  = KV0 + KV_BUF_WORDS;         // buf1
    uint32_t* Ps   = KV1 + KV_BUF_WORDS;         // per-warp [16][PS_STR]

    const int b    = blockIdx.x >> 5;
    const int pair = blockIdx.x & 31;
    const int tid  = threadIdx.x;
    const int wid  = tid >> 5;
    const int lane = tid & 31;
    const int r    = lane >> 2;                  // 0..7
    const int cq   = lane & 3;                   // 0..3
    const int w16  = wid * 16;
    uint32_t* Pw   = Ps + wid * 16 * PS_STR;

    const float* __restrict__ qg = g_q + (size_t)b * T * H;
    const float* __restrict__ kg = g_k + (size_t)b * T * H;
    const float* __restrict__ vg = g_v + (size_t)b * T * H;

    const int cp_row = tid >> 4;
    const int cp_c4  = (tid & 15) * 4;

    #pragma unroll 1
    for (int half = 0; half < 2; half++) {
        const int qt = (half == 0) ? pair : (63 - pair);
        const int q0 = qt * 64;
        const int ntiles = qt + 1;

        __syncthreads();    // previous half done with all buffers

        // ---- prefetch tile 0 into buf0 ----
        {
            uint32_t kdst = smem_u32(&KV0[cp_row * KS_STR + cp_c4]);
            uint32_t vdst = smem_u32(&KV0[64 * KS_STR + cp_row * VS_STR + cp_c4]);
            const float* ksrc = kg + (size_t)cp_row * H + cp_c4;
            const float* vsrc = vg + (size_t)cp_row * H + cp_c4;
            #pragma unroll
            for (int i = 0; i < 8; i++) {
                cp_async16(kdst + i * 8 * KS_STR * 4, ksrc + (size_t)i * 8 * H);
                cp_async16(vdst + i * 8 * VS_STR * 4, vsrc + (size_t)i * 8 * H);
            }
            CP_COMMIT();
        }

        // ---- load Q tile (scaled, rna tf32) while prefetch flies ----
        #pragma unroll
        for (int i = 0; i < 8; i++) {
            int f   = i * 128 + tid;
            int row = f >> 4;
            int c4  = (f & 15) * 4;
            float4 v = *(const float4*)(qg + (size_t)(q0 + row) * H + c4);
            *(uint4*)&Qs[row * QS_STR + c4] = make_uint4(
                f32_to_tf32(v.x * SCALE), f32_to_tf32(v.y * SCALE),
                f32_to_tf32(v.z * SCALE), f32_to_tf32(v.w * SCALE));
        }
        __syncthreads();

        uint32_t qa[8][4];
        #pragma unroll
        for (int ks = 0; ks < 8; ks++) {
            qa[ks][0] = Qs[(w16 + r)     * QS_STR + ks * 8 + cq];
            qa[ks][1] = Qs[(w16 + r + 8) * QS_STR + ks * 8 + cq];
            qa[ks][2] = Qs[(w16 + r)     * QS_STR + ks * 8 + cq + 4];
            qa[ks][3] = Qs[(w16 + r + 8) * QS_STR + ks * 8 + cq + 4];
        }

        float O[8][4];
        #pragma unroll
        for (int n = 0; n < 8; n++)
            #pragma unroll
            for (int j = 0; j < 4; j++) O[n][j] = 0.f;
        float m0h = -1e30f, m1h = -1e30f, l0 = 0.f, l1 = 0.f;

        const int tr0g = q0 + w16 + r;
        const int tr1g = tr0g + 8;

        for (int tile = 0; tile < ntiles; tile++) {
            uint32_t* KV  = (tile & 1) ? KV1 : KV0;
            uint32_t* Ks  = KV;
            uint32_t* Vs  = KV + 64 * KS_STR;

            CP_WAIT0();
            __syncthreads();

            if (tile + 1 < ntiles) {
                uint32_t* KVn = (tile & 1) ? KV0 : KV1;
                const int sn = (tile + 1) * 64;
                uint32_t kdst = smem_u32(&KVn[cp_row * KS_STR + cp_c4]);
                uint32_t vdst = smem_u32(&KVn[64 * KS_STR + cp_row * VS_STR + cp_c4]);
                const float* ksrc = kg + (size_t)(sn + cp_row) * H + cp_c4;
                const float* vsrc = vg + (size_t)(sn + cp_row) * H + cp_c4;
                #pragma unroll
                for (int i = 0; i < 8; i++) {
                    cp_async16(kdst + i * 8 * KS_STR * 4, ksrc + (size_t)i * 8 * H);
                    cp_async16(vdst + i * 8 * VS_STR * 4, vsrc + (size_t)i * 8 * H);
                }
                CP_COMMIT();
            }

            const int s0 = tile * 64;

            float S[8][4];
            #pragma unroll
            for (int n = 0; n < 8; n++) {
                #pragma unroll
                for (int j = 0; j < 4; j++) S[n][j] = 0.f;
            }
            #pragma unroll
            for (int n = 0; n < 8; n++) {
                const uint32_t* krow = &Ks[(n * 8 + r) * KS_STR + cq];
                #pragma unroll
                for (int ks = 0; ks < 8; ks++) {
                    uint32_t b0 = krow[ks * 8];
                    uint32_t b1 = krow[ks * 8 + 4];
                    mma_tf32(S[n], qa[ks][0], qa[ks][1], qa[ks][2], qa[ks][3], b0, b1);
                }
            }

            if (tile == qt) {
                #pragma unroll
                for (int n = 0; n < 8; n++) {
                    int col0 = s0 + n * 8 + 2 * cq;
                    int col1 = col0 + 1;
                    if (col0 > tr0g) S[n][0] = -1e30f;
                    if (col1 > tr0g) S[n][1] = -1e30f;
                    if (col0 > tr1g) S[n][2] = -1e30f;
                    if (col1 > tr1g) S[n][3] = -1e30f;
                }
            }

            float mx0 = -1e30f, mx1 = -1e30f;
            #pragma unroll
            for (int n = 0; n < 8; n++) {
                mx0 = fmaxf(mx0, fmaxf(S[n][0], S[n][1]));
                mx1 = fmaxf(mx1, fmaxf(S[n][2], S[n][3]));
            }
            mx0 = fmaxf(mx0, __shfl_xor_sync(0xffffffffu, mx0, 1));
            mx0 = fmaxf(mx0, __shfl_xor_sync(0xffffffffu, mx0, 2));
            mx1 = fmaxf(mx1, __shfl_xor_sync(0xffffffffu, mx1, 1));
            mx1 = fmaxf(mx1, __shfl_xor_sync(0xffffffffu, mx1, 2));

            float mn0 = fmaxf(m0h, mx0);
            float mn1 = fmaxf(m1h, mx1);
            float corr0 = __expf(m0h - mn0);
            float corr1 = __expf(m1h - mn1);
            m0h = mn0; m1h = mn1;

            float rs0 = 0.f, rs1 = 0.f;
            #pragma unroll
            for (int n = 0; n < 8; n++) {
                uint32_t p00 = f32_to_tf32(__expf(S[n][0] - mn0));
                uint32_t p01 = f32_to_tf32(__expf(S[n][1] - mn0));
                uint32_t p10 = f32_to_tf32(__expf(S[n][2] - mn1));
                uint32_t p11 = f32_to_tf32(__expf(S[n][3] - mn1));
                rs0 += __uint_as_float(p00) + __uint_as_float(p01);
                rs1 += __uint_as_float(p10) + __uint_as_float(p11);
                *(uint2*)&Pw[r       * PS_STR + n * 8 + 2 * cq] = make_uint2(p00, p01);
                *(uint2*)&Pw[(r + 8) * PS_STR + n * 8 + 2 * cq] = make_uint2(p10, p11);
            }
            rs0 += __shfl_xor_sync(0xffffffffu, rs0, 1);
            rs0 += __shfl_xor_sync(0xffffffffu, rs0, 2);
            rs1 += __shfl_xor_sync(0xffffffffu, rs1, 1);
            rs1 += __shfl_xor_sync(0xffffffffu, rs1, 2);
            l0 = l0 * corr0 + rs0;
            l1 = l1 * corr1 + rs1;

            #pragma unroll
            for (int n = 0; n < 8; n++) {
                O[n][0] *= corr0; O[n][1] *= corr0;
                O[n][2] *= corr1; O[n][3] *= corr1;
            }
            __syncwarp();

            #pragma unroll
            for (int ks = 0; ks < 8; ks++) {
                uint32_t a0 = Pw[r       * PS_STR + ks * 8 + cq];
                uint32_t a1 = Pw[(r + 8) * PS_STR + ks * 8 + cq];
                uint32_t a2 = Pw[r       * PS_STR + ks * 8 + cq + 4];
                uint32_t a3 = Pw[(r + 8) * PS_STR + ks * 8 + cq + 4];
                #pragma unroll
                for (int n = 0; n < 8; n++) {
                    uint32_t b0 = Vs[(ks * 8 + cq)     * VS_STR + n * 8 + r];
                    uint32_t b1 = Vs[(ks * 8 + cq + 4) * VS_STR + n * 8 + r];
                    mma_tf32(O[n], a0, a1, a2, a3, b0, b1);
                }
            }
            __syncwarp();
        }

        float inv0 = 1.0f / l0;
        float inv1 = 1.0f / l1;
        float* o0 = out + ((size_t)b * T + tr0g) * H;
        float* o1 = out + ((size_t)b * T + tr1g) * H;
        #pragma unroll
        for (int n = 0; n < 8; n++) {
            *(float2*)(o0 + n * 8 + 2 * cq) = make_float2(O[n][0] * inv0, O[n][1] * inv0);
            *(float2*)(o1 + n * 8 + 2 * cq) = make_float2(O[n][2] * inv1, O[n][3] * inv1);
        }
    }
}

// ---------------------------------------------------------------------------
extern "C" void kernel_launch(void* const* d_in, const int* in_sizes, int n_in,
                              void* d_out, int out_size)
{
    const float* x  = (const float*)d_in[0];
    const float* Wq = (const float*)d_in[1];
    const float* Wk = (const float*)d_in[2];
    const float* Wv = (const float*)d_in[3];
    float* out = (float*)d_out;

    static int attr_set = 0;
    const int pj_smem = PJ_SMEM_WORDS * 4;
    const int at_smem = AT_SMEM_WORDS * 4;
    if (!attr_set) {
        cudaFuncSetAttribute(proj_mma_kernel,
                             cudaFuncAttributeMaxDynamicSharedMemorySize, pj_smem);
        cudaFuncSetAttribute(attn_mma_kernel,
                             cudaFuncAttributeMaxDynamicSharedMemorySize, at_smem);
        attr_set = 1;
    }

    proj_mma_kernel<<<TOTROWS / 128, 256, pj_smem>>>(x, Wq, Wk, Wv);
    attn_mma_kernel<<<BATCH * 32, 128, at_smem>>>(out);
}